// round 2
// baseline (speedup 1.0000x reference)
#include <cuda_runtime.h>
#include <cstdint>

#define D 128
#define NVOX (D * D * D)
#define TPB 256
#define FULL 0xFFFFFFFFu

__global__ void __launch_bounds__(TPB, 8)
ca_update_kernel(const float* __restrict__ x,
                 const float* __restrict__ out,
                 float* __restrict__ y)
{
    __shared__ float sx[TPB * 5];   // staging: 1280 floats, reused for output

    const int tid  = threadIdx.x;
    const int base = blockIdx.x * TPB;
    const int v    = base + tid;
    const int lane = tid & 31;

    // ---- stage x in: coalesced float4 loads (320 per block) ----
    {
        const float4* xb = reinterpret_cast<const float4*>(x + (size_t)base * 5);
        float4* s4 = reinterpret_cast<float4*>(sx);
        #pragma unroll
        for (int t = tid; t < TPB * 5 / 4; t += TPB) s4[t] = xb[t];
    }
    __syncthreads();

    // ---- out: two coalesced-ish float4 loads ----
    const float4* o4 = reinterpret_cast<const float4*>(out + (size_t)v * 8);
    float4 oa = o4[0];   // 4 state logits
    float4 ob = o4[1];   // rot1 xyz + field

    // argmax, first-occurrence on ties
    int   state1 = 0;
    float best   = oa.x;
    if (oa.y > best) { best = oa.y; state1 = 1; }
    if (oa.z > best) { best = oa.z; state1 = 2; }
    if (oa.w > best) { best = oa.w; state1 = 3; }

    float s0f = sx[tid * 5 + 0];
    float y_e0 = sx[tid * 5 + 1];
    float y_e1 = sx[tid * 5 + 2];
    float y_e2 = sx[tid * 5 + 3];
    int state0 = (int)s0f;
    if (state0 == 0) state1 = 0;

    float field1 = ob.w;
    if (state1 <= 1) {
        field1 = -1.0f;
        y_e0 = -1.0f; y_e1 = -1.0f; y_e2 = -1.0f;
    } else if (state1 == 2) {
        field1 = fminf(fmaxf(field1, 0.0f), 0.92f);
    } else {
        field1 = 1.0f;
    }

    // ---- warp-cooperative neighbor argmin for flagged voxels ----
    bool flag = (state0 <= 1) && (state1 > 1);
    unsigned mask = __ballot_sync(FULL, flag);

    // lane-constant neighbor decode: lane t -> t-th of the 26 offsets
    // (lexicographic (di,dj,dk), center skipped)
    int c  = lane + (lane >= 13 ? 1 : 0);
    int di = c / 9 - 1;
    int dj = (c / 3) % 3 - 1;
    int dk = c % 3 - 1;
    int doff = (di * D + dj) * D * 5 + dk * 5;   // element offset in x

    while (mask) {
        int src = __ffs(mask) - 1;
        mask &= mask - 1;

        int   vv = __shfl_sync(FULL, v,    src);
        float rx = __shfl_sync(FULL, ob.x, src);
        float ry = __shfl_sync(FULL, ob.y, src);
        float rz = __shfl_sync(FULL, ob.z, src);

        int ki = vv >> 14;
        int kj = (vv >> 7) & (D - 1);
        int kk = vv & (D - 1);

        float n0 = 0.0f, n1 = 0.0f, n2 = 0.0f;
        if (lane < 26) {
            int ii = ki + di, jj = kj + dj, kz = kk + dk;
            if ((unsigned)ii < (unsigned)D &&
                (unsigned)jj < (unsigned)D &&
                (unsigned)kz < (unsigned)D) {
                const float* nb = x + (size_t)vv * 5 + doff + 1;
                n0 = nb[0];
                n1 = nb[1];
                n2 = nb[2];
            }
        }
        float d0 = n0 - rx;
        float d1 = n1 - ry;
        float d2 = n2 - rz;
        float dist = d0 * d0 + d1 * d1 + d2 * d2;

        // argmin over lanes 0..25, ties -> smallest lane (= neighbor order)
        unsigned bits = (lane < 26) ? __float_as_uint(dist) : 0xFFFFFFFFu;
        unsigned dmin = __reduce_min_sync(FULL, bits);
        unsigned win  = __ballot_sync(FULL, bits == dmin);
        int s = __ffs(win) - 1;

        float w0 = __shfl_sync(FULL, n0, s);
        float w1 = __shfl_sync(FULL, n1, s);
        float w2 = __shfl_sync(FULL, n2, s);
        if (lane == src) { y_e0 = w0; y_e1 = w1; y_e2 = w2; }
    }

    // ---- stage y out through smem, then coalesced float4 stores ----
    __syncthreads();            // all reads of sx are done
    sx[tid * 5 + 0] = (float)state1;
    sx[tid * 5 + 1] = y_e0;
    sx[tid * 5 + 2] = y_e1;
    sx[tid * 5 + 3] = y_e2;
    sx[tid * 5 + 4] = field1;
    __syncthreads();
    {
        float4* yb = reinterpret_cast<float4*>(y + (size_t)base * 5);
        const float4* s4 = reinterpret_cast<const float4*>(sx);
        #pragma unroll
        for (int t = tid; t < TPB * 5 / 4; t += TPB) yb[t] = s4[t];
    }
}

extern "C" void kernel_launch(void* const* d_in, const int* in_sizes, int n_in,
                              void* d_out, int out_size)
{
    const float* x   = (const float*)d_in[0];
    const float* out = (const float*)d_in[1];
    if (n_in >= 2 && in_sizes[0] == 8 * NVOX && in_sizes[1] == 5 * NVOX) {
        const float* t = x; x = out; out = t;
    }
    float* y = (float*)d_out;

    ca_update_kernel<<<NVOX / TPB, TPB>>>(x, out, y);
}